// round 1
// baseline (speedup 1.0000x reference)
#include <cuda_runtime.h>
#include <math.h>
#include <stdint.h>

// ---------------------------------------------------------------------------
// GATv2 2-layer: N=50000 nodes, E=800000 edges, 128 channels, heads 4 -> 1
// ---------------------------------------------------------------------------
#define N_NODES 50000
#define E_EDGES 800000
#define CH 128
#define NEG_SLOPE 0.2f

// Scratch (static device globals: allocation-free, allowed)
__device__ float    g_xl[N_NODES * CH];
__device__ float    g_xr[N_NODES * CH];
__device__ float    g_e[E_EDGES * 4];
__device__ unsigned g_mx[N_NODES * 4];
__device__ float    g_den[N_NODES * 4];
__device__ float    g_num[N_NODES * CH];
__device__ float    g_h[N_NODES * CH];

// Monotone float<->uint encoding so atomicMax(unsigned) == float max.
// memset(0) is the identity (0 < enc(-inf) = 0x007fffff).
__device__ __forceinline__ unsigned enc_f(float f) {
    unsigned b = __float_as_uint(f);
    return (b & 0x80000000u) ? ~b : (b | 0x80000000u);
}
__device__ __forceinline__ float dec_f(unsigned u) {
    unsigned b = (u & 0x80000000u) ? (u & 0x7fffffffu) : ~u;
    return __uint_as_float(b);
}

// ---------------------------------------------------------------------------
// Dual GEMM: out{L,R}[n, c] = sum_k in[n,k] * W{l,r}[k,c]
// 16 node-rows per block, 128 threads (one output column each), x tile in smem.
// N_NODES = 3125 * 16 exactly.
// ---------------------------------------------------------------------------
__global__ __launch_bounds__(128) void gemm_dual(
    const float* __restrict__ in,
    const float* __restrict__ Wl, const float* __restrict__ Wr,
    float* __restrict__ outL, float* __restrict__ outR)
{
    __shared__ float xs[16][CH];
    const int t = threadIdx.x;          // output column, 0..127
    const int base = blockIdx.x * 16;

    #pragma unroll
    for (int i = 0; i < 16; i++)
        xs[i][t] = in[(base + i) * CH + t];
    __syncthreads();

    float accL[16], accR[16];
    #pragma unroll
    for (int n = 0; n < 16; n++) { accL[n] = 0.f; accR[n] = 0.f; }

    #pragma unroll 4
    for (int k = 0; k < CH; k++) {
        const float wl = Wl[k * CH + t];
        const float wr = Wr[k * CH + t];
        #pragma unroll
        for (int n = 0; n < 16; n++) {
            const float xv = xs[n][k];
            accL[n] += xv * wl;
            accR[n] += xv * wr;
        }
    }

    #pragma unroll
    for (int n = 0; n < 16; n++) {
        outL[(base + n) * CH + t] = accL[n];
        outR[(base + n) * CH + t] = accR[n];
    }
}

// ---------------------------------------------------------------------------
// Edge scores: e[edge,h] = sum_c lrelu(xl[src,h,c] + xr[dst,h,c]) * att[h,c]
// One warp per edge; lane handles float4 chunk (channels 4l..4l+3).
// For H heads the 32/H-lane groups align exactly with heads.
// Also atomicMax of encoded e into mx[dst,h].
// ---------------------------------------------------------------------------
template <int H>
__global__ __launch_bounds__(256) void edge_score(
    const float* __restrict__ xl, const float* __restrict__ xr,
    const int* __restrict__ src, const int* __restrict__ dst,
    const float* __restrict__ att,
    float* __restrict__ e_out, unsigned* __restrict__ mx)
{
    const int warp = (blockIdx.x * blockDim.x + threadIdx.x) >> 5;
    const int lane = threadIdx.x & 31;
    if (warp >= E_EDGES) return;

    const int s = src[warp];
    const int d = dst[warp];

    const float4 a = ((const float4*)xl)[s * 32 + lane];
    const float4 b = ((const float4*)xr)[d * 32 + lane];
    const float4 w = ((const float4*)att)[lane];

    float m0 = a.x + b.x, m1 = a.y + b.y, m2 = a.z + b.z, m3 = a.w + b.w;
    m0 = (m0 > 0.f) ? m0 : NEG_SLOPE * m0;
    m1 = (m1 > 0.f) ? m1 : NEG_SLOPE * m1;
    m2 = (m2 > 0.f) ? m2 : NEG_SLOPE * m2;
    m3 = (m3 > 0.f) ? m3 : NEG_SLOPE * m3;

    float p = m0 * w.x + m1 * w.y + m2 * w.z + m3 * w.w;

    constexpr int G = 32 / H;          // lanes per head group (aligned)
    #pragma unroll
    for (int off = G / 2; off >= 1; off >>= 1)
        p += __shfl_xor_sync(0xffffffffu, p, off);

    if ((lane & (G - 1)) == 0) {
        const int h = lane / G;
        e_out[warp * H + h] = p;
        atomicMax(&mx[d * H + h], enc_f(p));
    }
}

// ---------------------------------------------------------------------------
// Edge aggregation: ex = exp(e - mx[dst]); den[dst,h] += ex;
// num[dst, h, c] += ex * xl[src, h, c]   (v4 reduction atomics)
// ---------------------------------------------------------------------------
template <int H>
__global__ __launch_bounds__(256) void edge_agg(
    const float* __restrict__ e_in, const unsigned* __restrict__ mx,
    const float* __restrict__ xl,
    const int* __restrict__ src, const int* __restrict__ dst,
    float* __restrict__ den, float* __restrict__ num)
{
    const int warp = (blockIdx.x * blockDim.x + threadIdx.x) >> 5;
    const int lane = threadIdx.x & 31;
    if (warp >= E_EDGES) return;

    const int s = src[warp];
    const int d = dst[warp];

    float ex = 0.f;
    if (lane < H) {
        const float e = e_in[warp * H + lane];
        const float m = dec_f(mx[d * H + lane]);
        ex = __expf(e - m);
        atomicAdd(&den[d * H + lane], ex);
    }
    // head owning this lane's float4 chunk (channels 4*lane .. 4*lane+3)
    constexpr int G = 32 / H;
    const float exh = __shfl_sync(0xffffffffu, ex, lane / G);

    float4 v = ((const float4*)xl)[s * 32 + lane];
    v.x *= exh; v.y *= exh; v.z *= exh; v.w *= exh;

    float* p = num + (size_t)d * CH + 4 * lane;
    asm volatile("red.global.add.v4.f32 [%0], {%1, %2, %3, %4};"
                 :: "l"(p), "f"(v.x), "f"(v.y), "f"(v.z), "f"(v.w)
                 : "memory");
}

// ---------------------------------------------------------------------------
// Finalize: out = num / max(den,!=0) + bias; optional ELU.
// ---------------------------------------------------------------------------
template <int H, bool ELU>
__global__ __launch_bounds__(256) void finalize(
    const float* __restrict__ num, const float* __restrict__ den,
    const float* __restrict__ bias, float* __restrict__ out)
{
    const int i = blockIdx.x * blockDim.x + threadIdx.x;
    if (i >= N_NODES * CH) return;
    const int c = i & (CH - 1);
    const int n = i >> 7;

    float dd = den[n * H + c / (CH / H)];
    if (dd == 0.f) dd = 1.f;
    float v = num[i] / dd + bias[c];
    if (ELU) v = (v > 0.f) ? v : expm1f(v);
    out[i] = v;
}

// ---------------------------------------------------------------------------
// Launch
// ---------------------------------------------------------------------------
extern "C" void kernel_launch(void* const* d_in, const int* in_sizes, int n_in,
                              void* d_out, int out_size)
{
    (void)in_sizes; (void)n_in; (void)out_size;

    const float* x    = (const float*)d_in[0];
    const int*   ei   = (const int*)  d_in[1];
    const float* W1l  = (const float*)d_in[2];
    const float* W1r  = (const float*)d_in[3];
    const float* att1 = (const float*)d_in[4];
    const float* b1   = (const float*)d_in[5];
    const float* W2l  = (const float*)d_in[6];
    const float* W2r  = (const float*)d_in[7];
    const float* att2 = (const float*)d_in[8];
    const float* b2   = (const float*)d_in[9];
    float* out = (float*)d_out;

    const int* src = ei;
    const int* dst = ei + E_EDGES;

    float *xl, *xr, *e, *den, *num, *h;
    unsigned* mx;
    cudaGetSymbolAddress((void**)&xl,  g_xl);
    cudaGetSymbolAddress((void**)&xr,  g_xr);
    cudaGetSymbolAddress((void**)&e,   g_e);
    cudaGetSymbolAddress((void**)&mx,  g_mx);
    cudaGetSymbolAddress((void**)&den, g_den);
    cudaGetSymbolAddress((void**)&num, g_num);
    cudaGetSymbolAddress((void**)&h,   g_h);

    const int EDGE_BLOCKS = E_EDGES / 8;          // 8 warps (edges) per block
    const int GEMM_BLOCKS = N_NODES / 16;         // 3125
    const int FIN_BLOCKS  = (N_NODES * CH + 255) / 256;

    // ---- Layer 1 (H=4) ----
    cudaMemsetAsync(mx,  0, N_NODES * 4 * sizeof(unsigned));
    cudaMemsetAsync(den, 0, N_NODES * 4 * sizeof(float));
    cudaMemsetAsync(num, 0, (size_t)N_NODES * CH * sizeof(float));

    gemm_dual<<<GEMM_BLOCKS, 128>>>(x, W1l, W1r, xl, xr);
    edge_score<4><<<EDGE_BLOCKS, 256>>>(xl, xr, src, dst, att1, e, mx);
    edge_agg<4><<<EDGE_BLOCKS, 256>>>(e, mx, xl, src, dst, den, num);
    finalize<4, true><<<FIN_BLOCKS, 256>>>(num, den, b1, h);

    // ---- Layer 2 (H=1) ----
    cudaMemsetAsync(mx,  0, N_NODES * sizeof(unsigned));
    cudaMemsetAsync(den, 0, N_NODES * sizeof(float));
    cudaMemsetAsync(num, 0, (size_t)N_NODES * CH * sizeof(float));

    gemm_dual<<<GEMM_BLOCKS, 128>>>(h, W2l, W2r, xl, xr);
    edge_score<1><<<EDGE_BLOCKS, 256>>>(xl, xr, src, dst, att2, e, mx);
    edge_agg<1><<<EDGE_BLOCKS, 256>>>(e, mx, xl, src, dst, den, num);
    finalize<1, false><<<FIN_BLOCKS, 256>>>(num, den, b2, out);
}

// round 2
// speedup vs baseline: 1.3001x; 1.3001x over previous
#include <cuda_runtime.h>
#include <math.h>
#include <stdint.h>

#define N_NODES 50000
#define E_EDGES 800000
#define CH 128
#define NEG_SLOPE 0.2f

// ---------------- scratch (static device globals) ----------------
__device__ float g_xl[N_NODES * CH];
__device__ float g_xr[N_NODES * CH];
__device__ float g_e[E_EDGES * 4];
__device__ float g_h[N_NODES * CH];
__device__ int   g_deg[N_NODES];
__device__ int   g_cur[N_NODES];
__device__ int   g_off[N_NODES + 1];
__device__ int2  g_pair[E_EDGES];       // (edge_id, src)

// ---------------------------------------------------------------------------
// CSR build
// ---------------------------------------------------------------------------
__global__ __launch_bounds__(256) void count_deg(const int* __restrict__ dst,
                                                 int* __restrict__ deg)
{
    const int i = blockIdx.x * 256 + threadIdx.x;
    if (i < E_EDGES) atomicAdd(&deg[dst[i]], 1);
}

__global__ __launch_bounds__(1024) void scan_deg(const int* __restrict__ deg,
                                                 int* __restrict__ off)
{
    __shared__ int wsum[32];
    __shared__ int carry_s;
    const int tid = threadIdx.x, lane = tid & 31, wid = tid >> 5;
    if (tid == 0) carry_s = 0;
    __syncthreads();

    for (int base = 0; base < N_NODES; base += 1024) {
        const int idx = base + tid;
        const int v = (idx < N_NODES) ? deg[idx] : 0;
        // inclusive warp scan
        int s = v;
        #pragma unroll
        for (int o = 1; o < 32; o <<= 1) {
            int t = __shfl_up_sync(0xffffffffu, s, o);
            if (lane >= o) s += t;
        }
        if (lane == 31) wsum[wid] = s;
        __syncthreads();
        if (wid == 0) {
            int ws = wsum[lane];
            #pragma unroll
            for (int o = 1; o < 32; o <<= 1) {
                int t = __shfl_up_sync(0xffffffffu, ws, o);
                if (lane >= o) ws += t;
            }
            wsum[lane] = ws;
        }
        __syncthreads();
        const int incl = s + (wid > 0 ? wsum[wid - 1] : 0);
        if (idx < N_NODES) off[idx] = carry_s + incl - v;   // exclusive
        const int total = wsum[31];
        __syncthreads();
        if (tid == 0) carry_s += total;
        __syncthreads();
    }
    if (tid == 0) off[N_NODES] = carry_s;
}

__global__ __launch_bounds__(256) void scatter_csr(
    const int* __restrict__ src, const int* __restrict__ dst,
    const int* __restrict__ off, int* __restrict__ cur,
    int2* __restrict__ pair)
{
    const int i = blockIdx.x * 256 + threadIdx.x;
    if (i >= E_EDGES) return;
    const int d = dst[i];
    const int p = off[d] + atomicAdd(&cur[d], 1);
    pair[p] = make_int2(i, src[i]);
}

// ---------------------------------------------------------------------------
// Dual GEMM: 32 rows/block, 128 threads; thread t -> column t of BOTH Wl, Wr.
// ---------------------------------------------------------------------------
__global__ __launch_bounds__(128) void gemm_dual(
    const float* __restrict__ in,
    const float* __restrict__ Wl, const float* __restrict__ Wr,
    float* __restrict__ outL, float* __restrict__ outR)
{
    __shared__ float4 xs4[32][32];      // [row][k4]
    const int t = threadIdx.x;
    const int base = blockIdx.x * 32;

    #pragma unroll
    for (int i = 0; i < 8; i++) {
        const int idx = t + i * 128;    // 0..1023
        const int row = idx >> 5;
        const int c4  = idx & 31;
        int grow = base + row;
        if (grow >= N_NODES) grow = N_NODES - 1;
        xs4[row][c4] = ((const float4*)in)[grow * 32 + c4];
    }
    __syncthreads();

    float accL[32], accR[32];
    #pragma unroll
    for (int n = 0; n < 32; n++) { accL[n] = 0.f; accR[n] = 0.f; }

    #pragma unroll 1
    for (int k4 = 0; k4 < 32; k4++) {
        const int k = 4 * k4;
        const float wl0 = Wl[(k + 0) * CH + t];
        const float wl1 = Wl[(k + 1) * CH + t];
        const float wl2 = Wl[(k + 2) * CH + t];
        const float wl3 = Wl[(k + 3) * CH + t];
        const float wr0 = Wr[(k + 0) * CH + t];
        const float wr1 = Wr[(k + 1) * CH + t];
        const float wr2 = Wr[(k + 2) * CH + t];
        const float wr3 = Wr[(k + 3) * CH + t];
        #pragma unroll
        for (int n = 0; n < 32; n++) {
            const float4 xv = xs4[n][k4];
            accL[n] += xv.x * wl0; accL[n] += xv.y * wl1;
            accL[n] += xv.z * wl2; accL[n] += xv.w * wl3;
            accR[n] += xv.x * wr0; accR[n] += xv.y * wr1;
            accR[n] += xv.z * wr2; accR[n] += xv.w * wr3;
        }
    }

    #pragma unroll
    for (int n = 0; n < 32; n++) {
        const int row = base + n;
        if (row < N_NODES) {
            outL[row * CH + t] = accL[n];
            outR[row * CH + t] = accR[n];
        }
    }
}

// ---------------------------------------------------------------------------
// Edge scores: e[edge,h] = sum_c lrelu(xl[src,h,c] + xr[dst,h,c]) * att[h,c]
// Warp per edge; lane owns channels 4l..4l+3 (head = l / (32/H)).
// ---------------------------------------------------------------------------
template <int H>
__global__ __launch_bounds__(256) void edge_score(
    const float* __restrict__ xl, const float* __restrict__ xr,
    const int* __restrict__ src, const int* __restrict__ dst,
    const float* __restrict__ att, float* __restrict__ e_out)
{
    const int warp = (blockIdx.x * blockDim.x + threadIdx.x) >> 5;
    const int lane = threadIdx.x & 31;
    if (warp >= E_EDGES) return;

    const int s = src[warp];
    const int d = dst[warp];

    const float4 a = ((const float4*)xl)[s * 32 + lane];
    const float4 b = ((const float4*)xr)[d * 32 + lane];
    const float4 w = ((const float4*)att)[lane];

    float m0 = a.x + b.x, m1 = a.y + b.y, m2 = a.z + b.z, m3 = a.w + b.w;
    m0 = (m0 > 0.f) ? m0 : NEG_SLOPE * m0;
    m1 = (m1 > 0.f) ? m1 : NEG_SLOPE * m1;
    m2 = (m2 > 0.f) ? m2 : NEG_SLOPE * m2;
    m3 = (m3 > 0.f) ? m3 : NEG_SLOPE * m3;

    float p = m0 * w.x + m1 * w.y + m2 * w.z + m3 * w.w;

    constexpr int G = 32 / H;
    #pragma unroll
    for (int off = G / 2; off >= 1; off >>= 1)
        p += __shfl_xor_sync(0xffffffffu, p, off);

    if ((lane & (G - 1)) == 0)
        e_out[warp * H + lane / G] = p;
}

// ---------------------------------------------------------------------------
// Gather aggregation: warp per destination node.
// pass1: segment max from e; pass2: den + sum(ex * xl[src]); writes output.
// ---------------------------------------------------------------------------
template <int H, bool ELU>
__global__ __launch_bounds__(256) void gather_agg(
    const float* __restrict__ xl, const float* __restrict__ e,
    const int* __restrict__ off, const int2* __restrict__ pair,
    const float* __restrict__ bias, float* __restrict__ out)
{
    const int node = (blockIdx.x * blockDim.x + threadIdx.x) >> 5;
    const int lane = threadIdx.x & 31;
    if (node >= N_NODES) return;

    const int s0 = off[node];
    const int s1 = off[node + 1];

    constexpr int G = 32 / H;
    const int h = lane / G;

    // pass 1: max of e over this node's edges, per head (group of G lanes splits edges)
    float m = -INFINITY;
    for (int i = s0 + (lane & (G - 1)); i < s1; i += G) {
        const int2 p = pair[i];
        m = fmaxf(m, e[p.x * H + h]);
    }
    #pragma unroll
    for (int o = G / 2; o >= 1; o >>= 1)
        m = fmaxf(m, __shfl_xor_sync(0xffffffffu, m, o));

    // pass 2: accumulate
    float4 acc = make_float4(0.f, 0.f, 0.f, 0.f);
    float den = 0.f;
    for (int i = s0; i < s1; i++) {
        const int2 p = pair[i];                       // warp-uniform
        const float ex = __expf(e[p.x * H + h] - m);
        den += ex;
        const float4 v = ((const float4*)xl)[p.y * 32 + lane];
        acc.x += ex * v.x; acc.y += ex * v.y;
        acc.z += ex * v.z; acc.w += ex * v.w;
    }
    if (den == 0.f) den = 1.f;
    const float inv = 1.f / den;

    float o0 = acc.x * inv + bias[4 * lane + 0];
    float o1 = acc.y * inv + bias[4 * lane + 1];
    float o2 = acc.z * inv + bias[4 * lane + 2];
    float o3 = acc.w * inv + bias[4 * lane + 3];
    if (ELU) {
        o0 = (o0 > 0.f) ? o0 : expm1f(o0);
        o1 = (o1 > 0.f) ? o1 : expm1f(o1);
        o2 = (o2 > 0.f) ? o2 : expm1f(o2);
        o3 = (o3 > 0.f) ? o3 : expm1f(o3);
    }
    ((float4*)out)[node * 32 + lane] = make_float4(o0, o1, o2, o3);
}

// ---------------------------------------------------------------------------
// Launch
// ---------------------------------------------------------------------------
extern "C" void kernel_launch(void* const* d_in, const int* in_sizes, int n_in,
                              void* d_out, int out_size)
{
    (void)in_sizes; (void)n_in; (void)out_size;

    const float* x    = (const float*)d_in[0];
    const int*   ei   = (const int*)  d_in[1];
    const float* W1l  = (const float*)d_in[2];
    const float* W1r  = (const float*)d_in[3];
    const float* att1 = (const float*)d_in[4];
    const float* b1   = (const float*)d_in[5];
    const float* W2l  = (const float*)d_in[6];
    const float* W2r  = (const float*)d_in[7];
    const float* att2 = (const float*)d_in[8];
    const float* b2   = (const float*)d_in[9];
    float* out = (float*)d_out;

    const int* src = ei;
    const int* dst = ei + E_EDGES;

    float *xl, *xr, *e, *h;
    int *deg, *cur, *off;
    int2 *pair;
    cudaGetSymbolAddress((void**)&xl,   g_xl);
    cudaGetSymbolAddress((void**)&xr,   g_xr);
    cudaGetSymbolAddress((void**)&e,    g_e);
    cudaGetSymbolAddress((void**)&h,    g_h);
    cudaGetSymbolAddress((void**)&deg,  g_deg);
    cudaGetSymbolAddress((void**)&cur,  g_cur);
    cudaGetSymbolAddress((void**)&off,  g_off);
    cudaGetSymbolAddress((void**)&pair, g_pair);

    const int EB   = (E_EDGES + 255) / 256;         // edge-parallel blocks
    const int EWB  = E_EDGES / 8;                   // warp-per-edge blocks
    const int GB   = (N_NODES + 31) / 32;           // gemm blocks
    const int NWB  = (N_NODES * 32 + 255) / 256;    // warp-per-node blocks

    // ---- CSR build (shared by both layers) ----
    cudaMemsetAsync(deg, 0, N_NODES * sizeof(int));
    cudaMemsetAsync(cur, 0, N_NODES * sizeof(int));
    count_deg<<<EB, 256>>>(dst, deg);
    scan_deg<<<1, 1024>>>(deg, off);
    scatter_csr<<<EB, 256>>>(src, dst, off, cur, pair);

    // ---- Layer 1 (H=4, ELU) ----
    gemm_dual<<<GB, 128>>>(x, W1l, W1r, xl, xr);
    edge_score<4><<<EWB, 256>>>(xl, xr, src, dst, att1, e);
    gather_agg<4, true><<<NWB, 256>>>(xl, e, off, pair, b1, h);

    // ---- Layer 2 (H=1) ----
    gemm_dual<<<GB, 128>>>(h, W2l, W2r, xl, xr);
    edge_score<1><<<EWB, 256>>>(xl, xr, src, dst, att2, e);
    gather_agg<1, false><<<NWB, 256>>>(xl, e, off, pair, b2, out);
}

// round 3
// speedup vs baseline: 1.8561x; 1.4276x over previous
#include <cuda_runtime.h>
#include <math.h>
#include <stdint.h>

#define N_NODES 50000
#define E_EDGES 800000
#define CH 128
#define NEG_SLOPE 0.2f

// ---------------- scratch (static device globals) ----------------
__device__ float g_xl[N_NODES * CH];
__device__ float g_xr[N_NODES * CH];
__device__ float g_h[N_NODES * CH];
__device__ int   g_deg[N_NODES];
__device__ int   g_cur[N_NODES];
__device__ int   g_off[N_NODES + 1];
__device__ int   g_srcs[E_EDGES];       // src ids, grouped by dst (CSR order)

// ---------------------------------------------------------------------------
// CSR build
// ---------------------------------------------------------------------------
__global__ __launch_bounds__(256) void count_deg(const int* __restrict__ dst,
                                                 int* __restrict__ deg)
{
    const int i = blockIdx.x * 256 + threadIdx.x;
    if (i < E_EDGES) atomicAdd(&deg[dst[i]], 1);
}

__global__ __launch_bounds__(1024) void scan_deg(const int* __restrict__ deg,
                                                 int* __restrict__ off)
{
    __shared__ int wsum[32];
    __shared__ int carry_s;
    const int tid = threadIdx.x, lane = tid & 31, wid = tid >> 5;
    if (tid == 0) carry_s = 0;
    __syncthreads();

    for (int base = 0; base < N_NODES; base += 1024) {
        const int idx = base + tid;
        const int v = (idx < N_NODES) ? deg[idx] : 0;
        int s = v;
        #pragma unroll
        for (int o = 1; o < 32; o <<= 1) {
            int t = __shfl_up_sync(0xffffffffu, s, o);
            if (lane >= o) s += t;
        }
        if (lane == 31) wsum[wid] = s;
        __syncthreads();
        if (wid == 0) {
            int ws = wsum[lane];
            #pragma unroll
            for (int o = 1; o < 32; o <<= 1) {
                int t = __shfl_up_sync(0xffffffffu, ws, o);
                if (lane >= o) ws += t;
            }
            wsum[lane] = ws;
        }
        __syncthreads();
        const int incl = s + (wid > 0 ? wsum[wid - 1] : 0);
        if (idx < N_NODES) off[idx] = carry_s + incl - v;   // exclusive
        const int total = wsum[31];
        __syncthreads();
        if (tid == 0) carry_s += total;
        __syncthreads();
    }
    if (tid == 0) off[N_NODES] = carry_s;
}

__global__ __launch_bounds__(256) void scatter_csr(
    const int* __restrict__ src, const int* __restrict__ dst,
    const int* __restrict__ off, int* __restrict__ cur,
    int* __restrict__ srcs)
{
    const int i = blockIdx.x * 256 + threadIdx.x;
    if (i >= E_EDGES) return;
    const int d = dst[i];
    const int p = off[d] + atomicAdd(&cur[d], 1);
    srcs[p] = src[i];
}

// ---------------------------------------------------------------------------
// Dual GEMM: 32 rows/block, 128 threads; thread t -> column t of BOTH Wl, Wr.
// ---------------------------------------------------------------------------
__global__ __launch_bounds__(128) void gemm_dual(
    const float* __restrict__ in,
    const float* __restrict__ Wl, const float* __restrict__ Wr,
    float* __restrict__ outL, float* __restrict__ outR)
{
    __shared__ float4 xs4[32][32];      // [row][k4]
    const int t = threadIdx.x;
    const int base = blockIdx.x * 32;

    #pragma unroll
    for (int i = 0; i < 8; i++) {
        const int idx = t + i * 128;
        const int row = idx >> 5;
        const int c4  = idx & 31;
        int grow = base + row;
        if (grow >= N_NODES) grow = N_NODES - 1;
        xs4[row][c4] = ((const float4*)in)[grow * 32 + c4];
    }
    __syncthreads();

    float accL[32], accR[32];
    #pragma unroll
    for (int n = 0; n < 32; n++) { accL[n] = 0.f; accR[n] = 0.f; }

    #pragma unroll 2
    for (int k4 = 0; k4 < 32; k4++) {
        const int k = 4 * k4;
        const float wl0 = Wl[(k + 0) * CH + t];
        const float wl1 = Wl[(k + 1) * CH + t];
        const float wl2 = Wl[(k + 2) * CH + t];
        const float wl3 = Wl[(k + 3) * CH + t];
        const float wr0 = Wr[(k + 0) * CH + t];
        const float wr1 = Wr[(k + 1) * CH + t];
        const float wr2 = Wr[(k + 2) * CH + t];
        const float wr3 = Wr[(k + 3) * CH + t];
        #pragma unroll
        for (int n = 0; n < 32; n++) {
            const float4 xv = xs4[n][k4];
            accL[n] += xv.x * wl0; accL[n] += xv.y * wl1;
            accL[n] += xv.z * wl2; accL[n] += xv.w * wl3;
            accR[n] += xv.x * wr0; accR[n] += xv.y * wr1;
            accR[n] += xv.z * wr2; accR[n] += xv.w * wr3;
        }
    }

    #pragma unroll
    for (int n = 0; n < 32; n++) {
        const int row = base + n;
        if (row < N_NODES) {
            outL[row * CH + t] = accL[n];
            outR[row * CH + t] = accR[n];
        }
    }
}

// ---------------------------------------------------------------------------
// Fused edge-score + online softmax + aggregation. Warp per destination node.
//
// Lane owns channels 4l..4l+3 (head h = lane / (32/H)). For each incoming
// edge: load xl[src] (once), score = sum_head lrelu(xl+xr)*att via 8-lane
// (or 32-lane) shuffle reduce, then online-softmax update of (mx, den, acc).
// Mathematically identical to max-then-exp segment softmax.
// ---------------------------------------------------------------------------
template <int H, bool ELU>
__global__ __launch_bounds__(256) void gather_fused(
    const float* __restrict__ xl, const float* __restrict__ xr,
    const float* __restrict__ att,
    const int* __restrict__ off, const int* __restrict__ srcs,
    const float* __restrict__ bias, float* __restrict__ out)
{
    const int node = (blockIdx.x * blockDim.x + threadIdx.x) >> 5;
    const int lane = threadIdx.x & 31;
    if (node >= N_NODES) return;

    const int s0 = off[node];
    const int s1 = off[node + 1];

    constexpr int G = 32 / H;

    const float4 b = ((const float4*)xr)[node * 32 + lane];
    const float4 w = ((const float4*)att)[lane];

    float  mx  = -INFINITY;
    float  den = 0.f;
    float4 acc = make_float4(0.f, 0.f, 0.f, 0.f);

    int s = (s0 < s1) ? srcs[s0] : 0;
    for (int i = s0; i < s1; i++) {
        const int s_next = (i + 1 < s1) ? srcs[i + 1] : 0;   // prefetch
        const float4 a = ((const float4*)xl)[s * 32 + lane];

        float m0 = a.x + b.x, m1 = a.y + b.y, m2 = a.z + b.z, m3 = a.w + b.w;
        m0 = (m0 > 0.f) ? m0 : NEG_SLOPE * m0;
        m1 = (m1 > 0.f) ? m1 : NEG_SLOPE * m1;
        m2 = (m2 > 0.f) ? m2 : NEG_SLOPE * m2;
        m3 = (m3 > 0.f) ? m3 : NEG_SLOPE * m3;
        float p = m0 * w.x + m1 * w.y + m2 * w.z + m3 * w.w;
        #pragma unroll
        for (int o = G / 2; o >= 1; o >>= 1)
            p += __shfl_xor_sync(0xffffffffu, p, o);   // e, same in group

        // online softmax update (per lane; group-consistent)
        const float nmx   = fmaxf(mx, p);
        const float scale = __expf(mx - nmx);          // exp(-inf)=0 first time
        const float ex    = __expf(p - nmx);
        den   = den * scale + ex;
        acc.x = acc.x * scale + ex * a.x;
        acc.y = acc.y * scale + ex * a.y;
        acc.z = acc.z * scale + ex * a.z;
        acc.w = acc.w * scale + ex * a.w;
        mx = nmx;
        s  = s_next;
    }

    if (den == 0.f) den = 1.f;
    const float inv = 1.f / den;

    float o0 = acc.x * inv + bias[4 * lane + 0];
    float o1 = acc.y * inv + bias[4 * lane + 1];
    float o2 = acc.z * inv + bias[4 * lane + 2];
    float o3 = acc.w * inv + bias[4 * lane + 3];
    if (ELU) {
        o0 = (o0 > 0.f) ? o0 : expm1f(o0);
        o1 = (o1 > 0.f) ? o1 : expm1f(o1);
        o2 = (o2 > 0.f) ? o2 : expm1f(o2);
        o3 = (o3 > 0.f) ? o3 : expm1f(o3);
    }
    ((float4*)out)[node * 32 + lane] = make_float4(o0, o1, o2, o3);
}

// ---------------------------------------------------------------------------
// Launch
// ---------------------------------------------------------------------------
extern "C" void kernel_launch(void* const* d_in, const int* in_sizes, int n_in,
                              void* d_out, int out_size)
{
    (void)in_sizes; (void)n_in; (void)out_size;

    const float* x    = (const float*)d_in[0];
    const int*   ei   = (const int*)  d_in[1];
    const float* W1l  = (const float*)d_in[2];
    const float* W1r  = (const float*)d_in[3];
    const float* att1 = (const float*)d_in[4];
    const float* b1   = (const float*)d_in[5];
    const float* W2l  = (const float*)d_in[6];
    const float* W2r  = (const float*)d_in[7];
    const float* att2 = (const float*)d_in[8];
    const float* b2   = (const float*)d_in[9];
    float* out = (float*)d_out;

    const int* src = ei;
    const int* dst = ei + E_EDGES;

    float *xl, *xr, *h;
    int *deg, *cur, *off, *srcs;
    cudaGetSymbolAddress((void**)&xl,   g_xl);
    cudaGetSymbolAddress((void**)&xr,   g_xr);
    cudaGetSymbolAddress((void**)&h,    g_h);
    cudaGetSymbolAddress((void**)&deg,  g_deg);
    cudaGetSymbolAddress((void**)&cur,  g_cur);
    cudaGetSymbolAddress((void**)&off,  g_off);
    cudaGetSymbolAddress((void**)&srcs, g_srcs);

    const int EB  = (E_EDGES + 255) / 256;
    const int GB  = (N_NODES + 31) / 32;
    const int NWB = (N_NODES * 32 + 255) / 256;

    // ---- CSR build (shared by both layers) ----
    cudaMemsetAsync(deg, 0, N_NODES * sizeof(int));
    cudaMemsetAsync(cur, 0, N_NODES * sizeof(int));
    count_deg<<<EB, 256>>>(dst, deg);
    scan_deg<<<1, 1024>>>(deg, off);
    scatter_csr<<<EB, 256>>>(src, dst, off, cur, srcs);

    // ---- Layer 1 (H=4, ELU) ----
    gemm_dual<<<GB, 128>>>(x, W1l, W1r, xl, xr);
    gather_fused<4, true><<<NWB, 256>>>(xl, xr, att1, off, srcs, b1, h);

    // ---- Layer 2 (H=1) ----
    gemm_dual<<<GB, 128>>>(h, W2l, W2r, xl, xr);
    gather_fused<1, false><<<NWB, 256>>>(xl, xr, att2, off, srcs, b2, out);
}